// round 1
// baseline (speedup 1.0000x reference)
#include <cuda_runtime.h>
#include <math.h>

#define BATCH 4096
#define DIM   1024
#define TEMB  256
#define NLAYERS 4

// ---------------- scratch (device globals: no allocations allowed) ----------
__device__ float g_h  [BATCH * DIM];        // residual stream
__device__ float g_xn [BATCH * DIM];        // normed/modulated activations
__device__ float g_ada[BATCH * 4 * DIM];    // adaLN params for current layer
__device__ float g_big[BATCH * 4 * DIM];    // v output / mlp hidden
__device__ float g_st [BATCH * TEMB];       // silu(t_emb)

// ---------------- epilogue modes --------------------------------------------
#define M_BIAS  0   // C = acc + bias
#define M_ADD   1   // C = acc + bias + extra
#define M_RESID 2   // C = C + acc + bias        (residual accumulate)
#define M_GELU  3   // C = gelu(acc + bias)      (exact erf)

// ---------------- tiled fp32 GEMM: C[M,N] = A[M,K] * W[N,K]^T ---------------
// Both operands K-contiguous (row-major "NT"): fully coalesced global loads.
// 128x128 tile, BK=16, 256 threads, 8x8 accum per thread.
template<int MODE>
__global__ __launch_bounds__(256) void gemm_nt(
    const float* __restrict__ A, const float* __restrict__ W,
    const float* __restrict__ bias, const float* __restrict__ extra,
    float* __restrict__ C, int M, int N, int K)
{
    __shared__ float As[16][132];
    __shared__ float Ws[16][132];

    const int bm  = blockIdx.y * 128;
    const int bn  = blockIdx.x * 128;
    const int tid = threadIdx.x;
    const int tx  = tid & 15;        // 0..15 -> 8 cols each
    const int ty  = tid >> 4;        // 0..15 -> 8 rows each
    const int lr  = tid >> 2;        // 0..63  load row
    const int lc  = (tid & 3) << 2;  // 0,4,8,12 load col (float4)

    float acc[8][8];
    #pragma unroll
    for (int i = 0; i < 8; i++)
        #pragma unroll
        for (int j = 0; j < 8; j++) acc[i][j] = 0.f;

    const float* Ap0 = A + (size_t)(bm + lr)      * K + lc;
    const float* Ap1 = A + (size_t)(bm + lr + 64) * K + lc;
    const float* Wp0 = W + (size_t)(bn + lr)      * K + lc;
    const float* Wp1 = W + (size_t)(bn + lr + 64) * K + lc;

    for (int k0 = 0; k0 < K; k0 += 16) {
        float4 a0 = *(const float4*)(Ap0 + k0);
        float4 a1 = *(const float4*)(Ap1 + k0);
        float4 w0 = *(const float4*)(Wp0 + k0);
        float4 w1 = *(const float4*)(Wp1 + k0);

        __syncthreads();   // previous iteration's reads done
        As[lc+0][lr]    = a0.x; As[lc+1][lr]    = a0.y; As[lc+2][lr]    = a0.z; As[lc+3][lr]    = a0.w;
        As[lc+0][lr+64] = a1.x; As[lc+1][lr+64] = a1.y; As[lc+2][lr+64] = a1.z; As[lc+3][lr+64] = a1.w;
        Ws[lc+0][lr]    = w0.x; Ws[lc+1][lr]    = w0.y; Ws[lc+2][lr]    = w0.z; Ws[lc+3][lr]    = w0.w;
        Ws[lc+0][lr+64] = w1.x; Ws[lc+1][lr+64] = w1.y; Ws[lc+2][lr+64] = w1.z; Ws[lc+3][lr+64] = w1.w;
        __syncthreads();

        #pragma unroll
        for (int kk = 0; kk < 16; kk++) {
            float4 av0 = *(const float4*)&As[kk][ty * 8];
            float4 av1 = *(const float4*)&As[kk][ty * 8 + 4];
            float4 bv0 = *(const float4*)&Ws[kk][tx * 8];
            float4 bv1 = *(const float4*)&Ws[kk][tx * 8 + 4];
            float a[8] = {av0.x, av0.y, av0.z, av0.w, av1.x, av1.y, av1.z, av1.w};
            float b[8] = {bv0.x, bv0.y, bv0.z, bv0.w, bv1.x, bv1.y, bv1.z, bv1.w};
            #pragma unroll
            for (int i = 0; i < 8; i++)
                #pragma unroll
                for (int j = 0; j < 8; j++)
                    acc[i][j] = fmaf(a[i], b[j], acc[i][j]);
        }
    }

    #pragma unroll
    for (int i = 0; i < 8; i++) {
        const int m = bm + ty * 8 + i;
        const size_t rowoff = (size_t)m * N;
        #pragma unroll
        for (int j = 0; j < 8; j++) {
            const int n = bn + tx * 8 + j;
            float v = acc[i][j] + bias[n];
            if (MODE == M_ADD)   v += extra[rowoff + n];
            if (MODE == M_RESID) v += C[rowoff + n];
            if (MODE == M_GELU)  v  = 0.5f * v * (1.f + erff(v * 0.70710678118654752f));
            C[rowoff + n] = v;
        }
    }
}

// ---------------- layernorm (+ optional adaLN modulation) -------------------
// one row per block, 256 threads x float4
__global__ __launch_bounds__(256) void ln_mod_k(
    const float* __restrict__ h, const float* __restrict__ g,
    const float* __restrict__ b, const float* __restrict__ ada,
    int so, int sho, float* __restrict__ out)
{
    const int row = blockIdx.x, t = threadIdx.x;
    float4 v = ((const float4*)(h + (size_t)row * DIM))[t];
    float s = v.x + v.y + v.z + v.w;
    float q = v.x*v.x + v.y*v.y + v.z*v.z + v.w*v.w;
    #pragma unroll
    for (int o = 16; o; o >>= 1) {
        s += __shfl_xor_sync(0xffffffffu, s, o);
        q += __shfl_xor_sync(0xffffffffu, q, o);
    }
    __shared__ float ss[8], qs[8];
    if ((t & 31) == 0) { ss[t >> 5] = s; qs[t >> 5] = q; }
    __syncthreads();
    s = 0.f; q = 0.f;
    #pragma unroll
    for (int i = 0; i < 8; i++) { s += ss[i]; q += qs[i]; }
    const float m   = s * (1.f / DIM);
    const float var = q * (1.f / DIM) - m * m;
    const float inv = rsqrtf(var + 1e-5f);

    const int c = t * 4;
    float4 o4;
    o4.x = (v.x - m) * inv * g[c+0] + b[c+0];
    o4.y = (v.y - m) * inv * g[c+1] + b[c+1];
    o4.z = (v.z - m) * inv * g[c+2] + b[c+2];
    o4.w = (v.w - m) * inv * g[c+3] + b[c+3];
    if (ada) {
        const float* ar = ada + (size_t)row * (4 * DIM);
        o4.x = o4.x * (1.f + ar[so + c+0]) + ar[sho + c+0];
        o4.y = o4.y * (1.f + ar[so + c+1]) + ar[sho + c+1];
        o4.z = o4.z * (1.f + ar[so + c+2]) + ar[sho + c+2];
        o4.w = o4.w * (1.f + ar[so + c+3]) + ar[sho + c+3];
    }
    ((float4*)(out + (size_t)row * DIM))[t] = o4;
}

// ---------------- silu ------------------------------------------------------
__global__ void silu_k(const float* __restrict__ in, float* __restrict__ out, int n)
{
    int i = blockIdx.x * blockDim.x + threadIdx.x;
    if (i < n) {
        float t = in[i];
        out[i] = t / (1.f + expf(-t));
    }
}

// ---------------- launch ----------------------------------------------------
extern "C" void kernel_launch(void* const* d_in, const int* in_sizes, int n_in,
                              void* d_out, int out_size)
{
    const float* x         = (const float*)d_in[0];
    const float* t_emb     = (const float*)d_in[1];
    const float* condition = (const float*)d_in[2];
    const float* in_w      = (const float*)d_in[3];
    const float* in_b      = (const float*)d_in[4];
    const float* ln1_g     = (const float*)d_in[5];
    const float* ln1_b     = (const float*)d_in[6];
    const float* wqkv      = (const float*)d_in[7];
    const float* bqkv      = (const float*)d_in[8];
    const float* wo        = (const float*)d_in[9];
    const float* bo        = (const float*)d_in[10];
    const float* ln2_g     = (const float*)d_in[11];
    const float* ln2_b     = (const float*)d_in[12];
    const float* w1        = (const float*)d_in[13];
    const float* b1        = (const float*)d_in[14];
    const float* w2        = (const float*)d_in[15];
    const float* b2        = (const float*)d_in[16];
    const float* ada_w     = (const float*)d_in[17];
    const float* ada_b     = (const float*)d_in[18];
    const float* out_ln_g  = (const float*)d_in[19];
    const float* out_ln_b  = (const float*)d_in[20];
    const float* out_w     = (const float*)d_in[21];
    const float* out_b     = (const float*)d_in[22];

    float *h, *xn, *ada, *big, *st;
    cudaGetSymbolAddress((void**)&h,   g_h);
    cudaGetSymbolAddress((void**)&xn,  g_xn);
    cudaGetSymbolAddress((void**)&ada, g_ada);
    cudaGetSymbolAddress((void**)&big, g_big);
    cudaGetSymbolAddress((void**)&st,  g_st);

    const dim3 blk(256);
    const dim3 grid_D (DIM / 128,     BATCH / 128);   // N=1024
    const dim3 grid_4D(4 * DIM / 128, BATCH / 128);   // N=4096

    // st = silu(t_emb)
    silu_k<<<(BATCH * TEMB + 255) / 256, 256>>>(t_emb, st, BATCH * TEMB);

    // h = x @ in_w^T + in_b + condition
    gemm_nt<M_ADD><<<grid_D, blk>>>(x, in_w, in_b, condition, h, BATCH, DIM, DIM);

    for (int l = 0; l < NLAYERS; l++) {
        const float* wqkv_l = wqkv  + (size_t)l * 3 * DIM * DIM;
        const float* bqkv_l = bqkv  + (size_t)l * 3 * DIM;
        const float* wo_l   = wo    + (size_t)l * DIM * DIM;
        const float* bo_l   = bo    + (size_t)l * DIM;
        const float* w1_l   = w1    + (size_t)l * 4 * DIM * DIM;
        const float* b1_l   = b1    + (size_t)l * 4 * DIM;
        const float* w2_l   = w2    + (size_t)l * DIM * 4 * DIM;
        const float* b2_l   = b2    + (size_t)l * DIM;
        const float* aw_l   = ada_w + (size_t)l * 4 * DIM * TEMB;
        const float* ab_l   = ada_b + (size_t)l * 4 * DIM;

        // ada = st @ ada_w^T + ada_b       [B, 4D], K=256
        gemm_nt<M_BIAS><<<grid_4D, blk>>>(st, aw_l, ab_l, nullptr, ada, BATCH, 4 * DIM, TEMB);

        // xn = ln(h)*(1+s1)+sh1
        ln_mod_k<<<BATCH, blk>>>(h, ln1_g + (size_t)l * DIM, ln1_b + (size_t)l * DIM,
                                 ada, 0, DIM, xn);

        // attention with seq_len==1: softmax==1 exactly => output = v.
        // v = xn @ wqkv[2D:3D]^T + bqkv[2D:3D]   (q,k never needed)
        gemm_nt<M_BIAS><<<grid_D, blk>>>(xn, wqkv_l + (size_t)2 * DIM * DIM,
                                         bqkv_l + 2 * DIM, nullptr, big, BATCH, DIM, DIM);

        // h += v @ wo^T + bo
        gemm_nt<M_RESID><<<grid_D, blk>>>(big, wo_l, bo_l, nullptr, h, BATCH, DIM, DIM);

        // xn = ln(h)*(1+s2)+sh2
        ln_mod_k<<<BATCH, blk>>>(h, ln2_g + (size_t)l * DIM, ln2_b + (size_t)l * DIM,
                                 ada, 2 * DIM, 3 * DIM, xn);

        // big = gelu(xn @ w1^T + b1)       [B, 4D]
        gemm_nt<M_GELU><<<grid_4D, blk>>>(xn, w1_l, b1_l, nullptr, big, BATCH, 4 * DIM, DIM);

        // h += big @ w2^T + b2             K=4096
        gemm_nt<M_RESID><<<grid_D, blk>>>(big, w2_l, b2_l, nullptr, h, BATCH, DIM, 4 * DIM);
    }

    // out = ln(h) @ out_w^T + out_b
    ln_mod_k<<<BATCH, blk>>>(h, out_ln_g, out_ln_b, nullptr, 0, 0, xn);
    gemm_nt<M_BIAS><<<grid_D, blk>>>(xn, out_w, out_b, nullptr, (float*)d_out, BATCH, DIM, DIM);
}